// round 1
// baseline (speedup 1.0000x reference)
#include <cuda_runtime.h>
#include <cstdint>

#define NIMG 4
#define NLVL 5
#define MTOT 4768
#define NEGV (-1e9f)
#define NMS_THR 0.7f
#define SCLAMP 4.135166556742356f

__device__ __forceinline__ int hwa_of(int l) { return 196608 >> (2 * l); }
__device__ __forceinline__ int k_of(int l) { return (l == 4) ? 768 : 1000; }

__device__ __forceinline__ unsigned int fkey(float f) {
    unsigned int u = __float_as_uint(f);
    return (u & 0x80000000u) ? ~u : (u | 0x80000000u);
}

// ---------------- scratch (device globals; no allocations) ----------------
__device__ unsigned int g_hist[20][4096];
__device__ unsigned int g_cnt[20];
__device__ unsigned int g_b1[20];
__device__ unsigned int g_rem[20];
__device__ unsigned int g_T24[20];
__device__ unsigned long long g_cand[20][8192];
__device__ int g_selidx[NIMG][MTOT];
__device__ float g_boxes[NIMG][MTOT][4];
__device__ float g_fscore[NIMG][MTOT];
__device__ unsigned char g_valid[NIMG][MTOT];
__device__ unsigned char g_kept[NIMG][MTOT];
__device__ int g_perm[NIMG][MTOT];

struct Ptrs {
    const float* logit[NLVL];
    const float* delta[NLVL];
    const float* anch[NLVL];
};

// ---------------- generic in-smem bitonic sort (ascending) ----------------
template <int SIZE, int NT>
__device__ void bitonic_asc(unsigned long long* s) {
    for (int size = 2; size <= SIZE; size <<= 1) {
        for (int stride = size >> 1; stride > 0; stride >>= 1) {
            __syncthreads();
            for (int t = threadIdx.x; t < SIZE / 2; t += NT) {
                int a = 2 * t - (t & (stride - 1));
                int b = a + stride;
                bool asc = ((a & size) == 0);
                unsigned long long x = s[a], y = s[b];
                if ((x > y) == asc) { s[a] = y; s[b] = x; }
            }
        }
    }
    __syncthreads();
}

// ---------------- stage 0: zero pass-1 histograms ----------------
__global__ void k_zero() {
    int i = blockIdx.x * blockDim.x + threadIdx.x;
    if (i < 20 * 4096) ((unsigned int*)g_hist)[i] = 0;
}

// ---------------- stage 1a: histogram of top-12 key bits ----------------
__global__ __launch_bounds__(256) void k_hist1(Ptrs P) {
    int p = blockIdx.y, n = p / NLVL, l = p % NLVL;
    int HWA = hwa_of(l);
    int start = blockIdx.x * 4096;
    if (start >= HWA) return;
    __shared__ unsigned int h[4096];
    for (int b = threadIdx.x; b < 4096; b += 256) h[b] = 0;
    __syncthreads();
    const float* base = P.logit[l] + (size_t)n * HWA;
    int end = min(start + 4096, HWA);
    for (int j = start + threadIdx.x; j < end; j += 256)
        atomicAdd(&h[fkey(base[j]) >> 20], 1u);
    __syncthreads();
    for (int b = threadIdx.x; b < 4096; b += 256) {
        unsigned int v = h[b];
        if (v) atomicAdd(&g_hist[p][b], v);
    }
}

// ---------------- threshold finder (pass=1: top bits, pass=2: mid bits) ----
__global__ __launch_bounds__(256) void k_thresh(int pass) {
    int p = blockIdx.x, l = p % NLVL;
    unsigned int target = (pass == 1) ? (unsigned int)k_of(l) : g_rem[p];
    int t = threadIdx.x;
    unsigned int loc[16], s = 0;
#pragma unroll
    for (int q = 0; q < 16; q++) {
        int r = t * 16 + q;
        loc[q] = g_hist[p][4095 - r];
        s += loc[q];
    }
    __shared__ unsigned int wb[8];
    int lane = t & 31, w = t >> 5;
    unsigned int x = s;
#pragma unroll
    for (int d = 1; d < 32; d <<= 1) {
        unsigned int y = __shfl_up_sync(0xFFFFFFFFu, x, d);
        if (lane >= d) x += y;
    }
    if (lane == 31) wb[w] = x;
    __syncthreads();
    if (w == 0 && lane < 8) {
        unsigned int ws = wb[lane], xx = ws;
#pragma unroll
        for (int d = 1; d < 8; d <<= 1) {
            unsigned int y = __shfl_up_sync(0xFFu, xx, d);
            if (lane >= d) xx += y;
        }
        wb[lane] = xx - ws;
    }
    __syncthreads();
    unsigned int ex = x - s + wb[w];
    if (ex < target && ex + s >= target) {
        unsigned int cum = ex;
#pragma unroll
        for (int q = 0; q < 16; q++) {
            if (cum + loc[q] >= target) {
                unsigned int bin = 4095u - (unsigned int)(t * 16 + q);
                if (pass == 1) { g_b1[p] = bin; g_rem[p] = target - cum; }
                else { g_T24[p] = (g_b1[p] << 12) | bin; g_cnt[p] = 0u; }
                break;
            }
            cum += loc[q];
        }
    }
    if (pass == 1) {
        __syncthreads();
#pragma unroll
        for (int q = 0; q < 16; q++) g_hist[p][t * 16 + q] = 0;
    }
}

// ---------------- stage 1b: refine histogram on mid-12 bits ----------------
__global__ __launch_bounds__(256) void k_hist2(Ptrs P) {
    int p = blockIdx.y, n = p / NLVL, l = p % NLVL;
    int HWA = hwa_of(l);
    int start = blockIdx.x * 4096;
    if (start >= HWA) return;
    unsigned int b1 = g_b1[p];
    __shared__ unsigned int h[4096];
    for (int b = threadIdx.x; b < 4096; b += 256) h[b] = 0;
    __syncthreads();
    const float* base = P.logit[l] + (size_t)n * HWA;
    int end = min(start + 4096, HWA);
    for (int j = start + threadIdx.x; j < end; j += 256) {
        unsigned int key = fkey(base[j]);
        if ((key >> 20) == b1) atomicAdd(&h[(key >> 8) & 0xFFFu], 1u);
    }
    __syncthreads();
    for (int b = threadIdx.x; b < 4096; b += 256) {
        unsigned int v = h[b];
        if (v) atomicAdd(&g_hist[p][b], v);
    }
}

// ---------------- stage 1c: collect candidates >= 24-bit threshold --------
__global__ __launch_bounds__(256) void k_collect(Ptrs P) {
    int p = blockIdx.y, n = p / NLVL, l = p % NLVL;
    int HWA = hwa_of(l);
    int start = blockIdx.x * 4096;
    if (start >= HWA) return;
    unsigned int T = g_T24[p];
    const float* base = P.logit[l] + (size_t)n * HWA;
    int end = min(start + 4096, HWA);
    for (int j = start + threadIdx.x; j < end; j += 256) {
        unsigned int key = fkey(base[j]);
        if ((key >> 8) >= T) {
            unsigned int pos = atomicAdd(&g_cnt[p], 1u);
            if (pos < 8192u)
                g_cand[p][pos] =
                    ((unsigned long long)key << 32) | (unsigned int)(~(unsigned int)j);
        }
    }
}

// ---------------- stage 1d: sort candidates, emit exact top-k -------------
__global__ __launch_bounds__(1024) void k_select() {
    extern __shared__ unsigned long long sh[];
    int p = blockIdx.x, n = p / NLVL, l = p % NLVL, k = k_of(l);
    unsigned int cnt = min(g_cnt[p], 8192u);
    for (int i = threadIdx.x; i < 8192; i += 1024)
        sh[i] = (i < (int)cnt) ? ~g_cand[p][i] : ~0ULL;
    bitonic_asc<8192, 1024>(sh);
    for (int t = threadIdx.x; t < k; t += 1024) {
        unsigned long long c = ~sh[t];
        int j = (int)(~(unsigned int)c);
        g_selidx[n][l * 1000 + t] = j;
    }
}

// ---------------- stage 2: decode selected boxes, clip, filter ------------
__global__ __launch_bounds__(256) void k_decode(Ptrs P) {
    int g = blockIdx.x * blockDim.x + threadIdx.x;
    if (g >= NIMG * MTOT) return;
    int n = g / MTOT, m = g % MTOT;
    int l = m / 1000;  // m<4768 -> l in [0,4]
    int HWA = hwa_of(l);
    int j = g_selidx[n][m];
    const float* a = P.anch[l] + 4 * (size_t)j;
    const float* d = P.delta[l] + 4 * ((size_t)n * HWA + j);
    float ax1 = a[0], ay1 = a[1], ax2 = a[2], ay2 = a[3];
    float wa = __fsub_rn(ax2, ax1), ha = __fsub_rn(ay2, ay1);
    float cxa = __fadd_rn(ax1, __fmul_rn(0.5f, wa));
    float cya = __fadd_rn(ay1, __fmul_rn(0.5f, ha));
    float dx = d[0], dy = d[1], dw = d[2], dh = d[3];
    dw = fminf(dw, SCLAMP);
    dh = fminf(dh, SCLAMP);
    float cx = __fadd_rn(__fmul_rn(dx, wa), cxa);
    float cy = __fadd_rn(__fmul_rn(dy, ha), cya);
    float w = __fmul_rn(wa, expf(dw));
    float h = __fmul_rn(ha, expf(dh));
    float x1 = __fsub_rn(cx, __fmul_rn(0.5f, w));
    float y1 = __fsub_rn(cy, __fmul_rn(0.5f, h));
    float x2 = __fadd_rn(cx, __fmul_rn(0.5f, w));
    float y2 = __fadd_rn(cy, __fmul_rn(0.5f, h));
    x1 = fminf(fmaxf(x1, 0.f), 1024.f);
    y1 = fminf(fmaxf(y1, 0.f), 1024.f);
    x2 = fminf(fmaxf(x2, 0.f), 1024.f);
    y2 = fminf(fmaxf(y2, 0.f), 1024.f);
    float ww = __fsub_rn(x2, x1), hh = __fsub_rn(y2, y1);
    bool valid = (ww > 0.f) && (hh > 0.f);
    float sc = P.logit[l][(size_t)n * HWA + j];
    g_boxes[n][m][0] = x1;
    g_boxes[n][m][1] = y1;
    g_boxes[n][m][2] = x2;
    g_boxes[n][m][3] = y2;
    g_valid[n][m] = valid ? 1 : 0;
    g_fscore[n][m] = valid ? sc : NEGV;
}

// ---------------- stage 3: per-image global sort (score desc, idx asc) ----
__global__ __launch_bounds__(1024) void k_gsort() {
    extern __shared__ unsigned long long sh[];
    int n = blockIdx.x;
    for (int i = threadIdx.x; i < 8192; i += 1024) {
        if (i < MTOT) {
            unsigned int key = fkey(g_fscore[n][i]);
            unsigned long long c =
                ((unsigned long long)key << 13) | (unsigned long long)(8191 - i);
            sh[i] = ~c;
        } else {
            sh[i] = ~0ULL;
        }
    }
    bitonic_asc<8192, 1024>(sh);
    for (int r = threadIdx.x; r < MTOT; r += 1024) {
        unsigned long long c = ~sh[r];
        g_perm[n][r] = 8191 - (int)(c & 0x1FFFULL);
    }
}

// ---------------- stage 4: per-(image,level) greedy NMS -------------------
__global__ __launch_bounds__(1024) void k_nms() {
    int p = blockIdx.x, n = p / NLVL, l = p % NLVL;
    int k = k_of(l), off = l * 1000;
    __shared__ float sx1[1000], sy1[1000], sx2[1000], sy2[1000], sar[1000];
    __shared__ unsigned char st[1000];  // 0 alive, 1 invalid, 2 suppressed
    int t = threadIdx.x;
    float offc = (float)l * 2048.0f;  // LVL_OFFSET trick (matches reference rounding)
    float mx1 = 0, my1 = 0, mx2 = 0, my2 = 0, mar = 0;
    if (t < k) {
        float a = __fadd_rn(g_boxes[n][off + t][0], offc);
        float b = __fadd_rn(g_boxes[n][off + t][1], offc);
        float c = __fadd_rn(g_boxes[n][off + t][2], offc);
        float d = __fadd_rn(g_boxes[n][off + t][3], offc);
        float ar = __fmul_rn(__fsub_rn(c, a), __fsub_rn(d, b));
        sx1[t] = a; sy1[t] = b; sx2[t] = c; sy2[t] = d; sar[t] = ar;
        mx1 = a; my1 = b; mx2 = c; my2 = d; mar = ar;
        st[t] = g_valid[n][off + t] ? 0 : 1;
    }
    __syncthreads();
    for (int i = 0; i < k; i++) {
        if (st[i] == 0) {  // uniform across block
            float ax1 = sx1[i], ay1 = sy1[i], ax2 = sx2[i], ay2 = sy2[i], aa = sar[i];
            if (t > i && t < k && st[t] == 0) {
                float lx = fmaxf(ax1, mx1), ly = fmaxf(ay1, my1);
                float rx = fminf(ax2, mx2), ry = fminf(ay2, my2);
                float w = fmaxf(__fsub_rn(rx, lx), 0.f);
                float h = fmaxf(__fsub_rn(ry, ly), 0.f);
                float inter = __fmul_rn(w, h);
                float den = __fadd_rn(__fsub_rn(__fadd_rn(aa, mar), inter), 1e-9f);
                if (__fdiv_rn(inter, den) > NMS_THR) st[t] = 2;
            }
            __syncthreads();
        }
    }
    if (t < k) g_kept[n][off + t] = (st[t] == 0) ? 1 : 0;
}

// ---------------- stage 5: stable partition -> first 1000 outputs ---------
__global__ __launch_bounds__(1024) void k_final(float* out) {
    int n = blockIdx.x, t = threadIdx.x;
    __shared__ int wb[33];
    int f[5], mloc[5];
    int ls = 0;
#pragma unroll
    for (int q = 0; q < 5; q++) {
        int r = t * 5 + q;
        if (r < MTOT) {
            int m = g_perm[n][r];
            mloc[q] = m;
            f[q] = g_kept[n][m];
        } else {
            mloc[q] = 0;
            f[q] = 0;
        }
        ls += f[q];
    }
    int lane = t & 31, w = t >> 5;
    int x = ls;
#pragma unroll
    for (int d = 1; d < 32; d <<= 1) {
        int y = __shfl_up_sync(0xFFFFFFFFu, x, d);
        if (lane >= d) x += y;
    }
    if (lane == 31) wb[w] = x;
    __syncthreads();
    if (w == 0) {
        int ws = wb[lane], xx = ws;
#pragma unroll
        for (int d = 1; d < 32; d <<= 1) {
            int y = __shfl_up_sync(0xFFFFFFFFu, xx, d);
            if (lane >= d) xx += y;
        }
        wb[lane] = xx - ws;
        if (lane == 31) wb[32] = xx;
    }
    __syncthreads();
    int KT = wb[32];
    int kr = x - ls + wb[w];
#pragma unroll
    for (int q = 0; q < 5; q++) {
        int r = t * 5 + q;
        if (r < MTOT) {
            int pos = f[q] ? kr : KT + (r - kr);
            if (pos < 1000) {
                int m = mloc[q];
                out[((size_t)n * 1000 + pos) * 4 + 0] = g_boxes[n][m][0];
                out[((size_t)n * 1000 + pos) * 4 + 1] = g_boxes[n][m][1];
                out[((size_t)n * 1000 + pos) * 4 + 2] = g_boxes[n][m][2];
                out[((size_t)n * 1000 + pos) * 4 + 3] = g_boxes[n][m][3];
                out[NIMG * 1000 * 4 + (size_t)n * 1000 + pos] =
                    f[q] ? g_fscore[n][m] : NEGV;
            }
            kr += f[q];
        }
    }
}

// ---------------- host launcher ----------------
extern "C" void kernel_launch(void* const* d_in, const int* in_sizes, int n_in,
                              void* d_out, int out_size) {
    Ptrs P;
    // Detect input ordering: interleaved (logits,deltas,anchors per level) vs grouped.
    bool interleaved = (n_in >= 2 && in_sizes[1] == 3145728);
    for (int l = 0; l < NLVL; l++) {
        if (interleaved) {
            P.logit[l] = (const float*)d_in[3 * l + 0];
            P.delta[l] = (const float*)d_in[3 * l + 1];
            P.anch[l] = (const float*)d_in[3 * l + 2];
        } else {
            P.logit[l] = (const float*)d_in[l];
            P.delta[l] = (const float*)d_in[5 + l];
            P.anch[l] = (const float*)d_in[10 + l];
        }
    }
    float* out = (float*)d_out;

    cudaFuncSetAttribute(k_select, cudaFuncAttributeMaxDynamicSharedMemorySize, 65536);
    cudaFuncSetAttribute(k_gsort, cudaFuncAttributeMaxDynamicSharedMemorySize, 65536);

    k_zero<<<80, 1024>>>();
    k_hist1<<<dim3(48, 20), 256>>>(P);
    k_thresh<<<20, 256>>>(1);
    k_hist2<<<dim3(48, 20), 256>>>(P);
    k_thresh<<<20, 256>>>(2);
    k_collect<<<dim3(48, 20), 256>>>(P);
    k_select<<<20, 1024, 65536>>>();
    k_decode<<<(NIMG * MTOT + 255) / 256, 256>>>(P);
    k_gsort<<<4, 1024, 65536>>>();
    k_nms<<<20, 1024>>>();
    k_final<<<4, 1024>>>(out);
}

// round 2
// speedup vs baseline: 2.9314x; 2.9314x over previous
#include <cuda_runtime.h>
#include <cstdint>

#define NIMG 4
#define NLVL 5
#define MTOT 4768
#define NEGV (-1e9f)
#define NMS_THR 0.7f
#define SCLAMP 4.135166556742356f

__device__ __forceinline__ int hwa_of(int l) { return 196608 >> (2 * l); }
__device__ __forceinline__ int k_of(int l) { return (l == 4) ? 768 : 1000; }

__device__ __forceinline__ unsigned int fkey(float f) {
    unsigned int u = __float_as_uint(f);
    return (u & 0x80000000u) ? ~u : (u | 0x80000000u);
}

// ---------------- scratch (device globals; no allocations) ----------------
__device__ unsigned int g_hist[20][4096];
__device__ unsigned int g_cnt[20];
__device__ unsigned int g_b1[20];
__device__ unsigned long long g_cand[20][8192];
__device__ int g_selidx[NIMG][MTOT];
__device__ float g_boxes[NIMG][MTOT][4];
__device__ float g_fscore[NIMG][MTOT];
__device__ unsigned char g_valid[NIMG][MTOT];
__device__ unsigned char g_kept[NIMG][MTOT];
__device__ int g_perm[NIMG][MTOT];
__device__ unsigned long long g_mask[20][1000][16];

struct Ptrs {
    const float* logit[NLVL];
    const float* delta[NLVL];
    const float* anch[NLVL];
};

// ---------------- stage 0: zero histograms ----------------
__global__ void k_zero() {
    int i = blockIdx.x * blockDim.x + threadIdx.x;
    if (i < 20 * 4096) ((unsigned int*)g_hist)[i] = 0;
}

// ---------------- stage 1a: histogram of top-12 key bits ----------------
__global__ __launch_bounds__(256) void k_hist(Ptrs P) {
    int p = blockIdx.y, n = p / NLVL, l = p % NLVL;
    int HWA = hwa_of(l);
    int start = blockIdx.x * 8192;
    if (start >= HWA) return;
    __shared__ unsigned int h[4096];
    for (int b = threadIdx.x; b < 4096; b += 256) h[b] = 0;
    __syncthreads();
    const float4* base = (const float4*)(P.logit[l] + (size_t)n * HWA);
    int s4 = start >> 2, e4 = min(start + 8192, HWA) >> 2;
    for (int j = s4 + threadIdx.x; j < e4; j += 256) {
        float4 v = base[j];
        atomicAdd(&h[fkey(v.x) >> 20], 1u);
        atomicAdd(&h[fkey(v.y) >> 20], 1u);
        atomicAdd(&h[fkey(v.z) >> 20], 1u);
        atomicAdd(&h[fkey(v.w) >> 20], 1u);
    }
    __syncthreads();
    for (int b = threadIdx.x; b < 4096; b += 256) {
        unsigned int v = h[b];
        if (v) atomicAdd(&g_hist[p][b], v);
    }
}

// ---------------- stage 1b: find 12-bit threshold bin ----------------
__global__ __launch_bounds__(256) void k_thresh() {
    int p = blockIdx.x, l = p % NLVL;
    unsigned int target = (unsigned int)k_of(l);
    int t = threadIdx.x;
    unsigned int loc[16], s = 0;
#pragma unroll
    for (int q = 0; q < 16; q++) {
        int r = t * 16 + q;
        loc[q] = g_hist[p][4095 - r];
        s += loc[q];
    }
    __shared__ unsigned int wb[8];
    int lane = t & 31, w = t >> 5;
    unsigned int x = s;
#pragma unroll
    for (int d = 1; d < 32; d <<= 1) {
        unsigned int y = __shfl_up_sync(0xFFFFFFFFu, x, d);
        if (lane >= d) x += y;
    }
    if (lane == 31) wb[w] = x;
    __syncthreads();
    if (w == 0 && lane < 8) {
        unsigned int ws = wb[lane], xx = ws;
#pragma unroll
        for (int d = 1; d < 8; d <<= 1) {
            unsigned int y = __shfl_up_sync(0xFFu, xx, d);
            if (lane >= d) xx += y;
        }
        wb[lane] = xx - ws;
    }
    __syncthreads();
    unsigned int ex = x - s + wb[w];
    if (ex < target && ex + s >= target) {
        unsigned int cum = ex;
#pragma unroll
        for (int q = 0; q < 16; q++) {
            if (cum + loc[q] >= target) {
                g_b1[p] = 4095u - (unsigned int)(t * 16 + q);
                g_cnt[p] = 0u;
                break;
            }
            cum += loc[q];
        }
    }
}

// ---------------- stage 1c: collect candidates >= 12-bit threshold --------
__global__ __launch_bounds__(256) void k_collect(Ptrs P) {
    int p = blockIdx.y, n = p / NLVL, l = p % NLVL;
    int HWA = hwa_of(l);
    int start = blockIdx.x * 8192;
    if (start >= HWA) return;
    unsigned int b1 = g_b1[p];
    const float4* base = (const float4*)(P.logit[l] + (size_t)n * HWA);
    int s4 = start >> 2, e4 = min(start + 8192, HWA) >> 2;
    for (int j4 = s4 + threadIdx.x; j4 < e4; j4 += 256) {
        float4 v = base[j4];
        float vv[4] = {v.x, v.y, v.z, v.w};
#pragma unroll
        for (int q = 0; q < 4; q++) {
            unsigned int key = fkey(vv[q]);
            if ((key >> 20) >= b1) {
                unsigned int pos = atomicAdd(&g_cnt[p], 1u);
                if (pos < 8192u) {
                    int j = 4 * j4 + q;
                    g_cand[p][pos] = ((unsigned long long)key << 32) |
                                     (unsigned int)(~(unsigned int)j);
                }
            }
        }
    }
}

// ---------------- stage 1d: dynamic-size bitonic sort, emit top-k ---------
__global__ __launch_bounds__(1024) void k_select() {
    extern __shared__ unsigned long long sh[];
    int p = blockIdx.x, n = p / NLVL, l = p % NLVL, k = k_of(l);
    unsigned int cnt = min(g_cnt[p], 8192u);
    int size = 1024;
    while (size < (int)cnt) size <<= 1;
    for (int i = threadIdx.x; i < size; i += 1024)
        sh[i] = (i < (int)cnt) ? ~g_cand[p][i] : ~0ULL;
    for (int s = 2; s <= size; s <<= 1) {
        for (int st = s >> 1; st > 0; st >>= 1) {
            __syncthreads();
            int half = size >> 1;
            for (int tt = threadIdx.x; tt < half; tt += 1024) {
                int a = 2 * tt - (tt & (st - 1));
                int b = a + st;
                bool asc = ((a & s) == 0);
                unsigned long long x = sh[a], y = sh[b];
                if ((x > y) == asc) { sh[a] = y; sh[b] = x; }
            }
        }
    }
    __syncthreads();
    for (int t = threadIdx.x; t < k; t += 1024) {
        unsigned long long c = ~sh[t];
        g_selidx[n][l * 1000 + t] = (int)(~(unsigned int)c);
    }
}

// ---------------- stage 2: decode selected boxes, clip, filter ------------
__global__ __launch_bounds__(256) void k_decode(Ptrs P) {
    int g = blockIdx.x * blockDim.x + threadIdx.x;
    if (g >= NIMG * MTOT) return;
    int n = g / MTOT, m = g % MTOT;
    int l = m / 1000;
    int HWA = hwa_of(l);
    int j = g_selidx[n][m];
    const float* a = P.anch[l] + 4 * (size_t)j;
    const float* d = P.delta[l] + 4 * ((size_t)n * HWA + j);
    float ax1 = a[0], ay1 = a[1], ax2 = a[2], ay2 = a[3];
    float wa = __fsub_rn(ax2, ax1), ha = __fsub_rn(ay2, ay1);
    float cxa = __fadd_rn(ax1, __fmul_rn(0.5f, wa));
    float cya = __fadd_rn(ay1, __fmul_rn(0.5f, ha));
    float dx = d[0], dy = d[1], dw = d[2], dh = d[3];
    dw = fminf(dw, SCLAMP);
    dh = fminf(dh, SCLAMP);
    float cx = __fadd_rn(__fmul_rn(dx, wa), cxa);
    float cy = __fadd_rn(__fmul_rn(dy, ha), cya);
    float w = __fmul_rn(wa, expf(dw));
    float h = __fmul_rn(ha, expf(dh));
    float x1 = __fsub_rn(cx, __fmul_rn(0.5f, w));
    float y1 = __fsub_rn(cy, __fmul_rn(0.5f, h));
    float x2 = __fadd_rn(cx, __fmul_rn(0.5f, w));
    float y2 = __fadd_rn(cy, __fmul_rn(0.5f, h));
    x1 = fminf(fmaxf(x1, 0.f), 1024.f);
    y1 = fminf(fmaxf(y1, 0.f), 1024.f);
    x2 = fminf(fmaxf(x2, 0.f), 1024.f);
    y2 = fminf(fmaxf(y2, 0.f), 1024.f);
    float ww = __fsub_rn(x2, x1), hh = __fsub_rn(y2, y1);
    bool valid = (ww > 0.f) && (hh > 0.f);
    float sc = P.logit[l][(size_t)n * HWA + j];
    g_boxes[n][m][0] = x1;
    g_boxes[n][m][1] = y1;
    g_boxes[n][m][2] = x2;
    g_boxes[n][m][3] = y2;
    g_valid[n][m] = valid ? 1 : 0;
    g_fscore[n][m] = valid ? sc : NEGV;
}

// ---------------- block scan helper (1024 threads, exclusive) -------------
__device__ __forceinline__ int scan1024(int v, int* total, int* sw) {
    __syncthreads();  // protect sw reuse
    int lane = threadIdx.x & 31, w = threadIdx.x >> 5;
    int x = v;
#pragma unroll
    for (int d = 1; d < 32; d <<= 1) {
        int y = __shfl_up_sync(0xFFFFFFFFu, x, d);
        if (lane >= d) x += y;
    }
    if (lane == 31) sw[w] = x;
    __syncthreads();
    if (w == 0) {
        int ws = sw[lane], xx = ws;
#pragma unroll
        for (int d = 1; d < 32; d <<= 1) {
            int y = __shfl_up_sync(0xFFFFFFFFu, xx, d);
            if (lane >= d) xx += y;
        }
        sw[lane] = xx - ws;
        if (lane == 31) sw[32] = xx;
    }
    __syncthreads();
    *total = sw[32];
    return x - v + sw[w];
}

// ---------------- stage 3: per-level partition + 5-way merge ranks --------
__global__ __launch_bounds__(1024) void k_merge() {
    __shared__ unsigned long long comp[MTOT];
    __shared__ int sw[33];
    int n = blockIdx.x, t = threadIdx.x;
    for (int l = 0; l < NLVL; l++) {
        int k = k_of(l), off = l * 1000;
        int flag = 0;
        unsigned long long c = 0;
        if (t < k) {
            flag = g_valid[n][off + t];
            unsigned int key = fkey(g_fscore[n][off + t]);
            c = ((unsigned long long)(~key) << 32) | (unsigned int)(off + t);
        }
        int tot;
        int r = scan1024(flag, &tot, sw);
        if (t < k) {
            int dest = flag ? r : tot + (t - r);
            comp[off + dest] = c;
        }
    }
    __syncthreads();
    for (int e = t; e < MTOT; e += 1024) {
        int l = e / 1000;
        unsigned long long c = comp[e];
        int rank = e - l * 1000;
#pragma unroll
        for (int l2 = 0; l2 < NLVL; l2++) {
            if (l2 == l) continue;
            int base = l2 * 1000, len = k_of(l2);
            int lo = 0, hi = len;
            while (lo < hi) {
                int mid = (lo + hi) >> 1;
                if (comp[base + mid] < c) lo = mid + 1;
                else hi = mid;
            }
            rank += lo;
        }
        g_perm[n][rank] = (int)(unsigned int)(c & 0xFFFFFFFFULL);
    }
}

// ---------------- stage 4a: suppression bitmask (IoU > thr, j > i) --------
__global__ __launch_bounds__(256) void k_iou() {
    int p = blockIdx.y, n = p / NLVL, l = p % NLVL, k = k_of(l);
    int rb = blockIdx.x;
    if (rb * 64 >= k) return;
    __shared__ float sx1[1000], sy1[1000], sx2[1000], sy2[1000], sar[1000];
    float offc = (float)l * 2048.0f;
    int off = l * 1000;
    for (int i = threadIdx.x; i < k; i += 256) {
        float a = __fadd_rn(g_boxes[n][off + i][0], offc);
        float b = __fadd_rn(g_boxes[n][off + i][1], offc);
        float c = __fadd_rn(g_boxes[n][off + i][2], offc);
        float d = __fadd_rn(g_boxes[n][off + i][3], offc);
        sx1[i] = a; sy1[i] = b; sx2[i] = c; sy2[i] = d;
        sar[i] = __fmul_rn(__fsub_rn(c, a), __fsub_rn(d, b));
    }
    __syncthreads();
    int i = rb * 64 + (threadIdx.x >> 2);
    if (i >= k) return;
    int wg = threadIdx.x & 3;
    float ax1 = sx1[i], ay1 = sy1[i], ax2 = sx2[i], ay2 = sy2[i], aa = sar[i];
#pragma unroll
    for (int q = 0; q < 4; q++) {
        int w = wg * 4 + q;
        int j0 = w * 64;
        unsigned long long bits = 0;
        if (j0 < k) {
            int jend = min(j0 + 64, k);
            for (int j = max(j0, i + 1); j < jend; j++) {
                float lx = fmaxf(ax1, sx1[j]), ly = fmaxf(ay1, sy1[j]);
                float rx = fminf(ax2, sx2[j]), ry = fminf(ay2, sy2[j]);
                float w_ = fmaxf(__fsub_rn(rx, lx), 0.f);
                float h_ = fmaxf(__fsub_rn(ry, ly), 0.f);
                float inter = __fmul_rn(w_, h_);
                float den = __fadd_rn(__fsub_rn(__fadd_rn(aa, sar[j]), inter), 1e-9f);
                if (inter > 0.f && __fdiv_rn(inter, den) > NMS_THR)
                    bits |= 1ULL << (j - j0);
            }
        }
        g_mask[p][i][w] = bits;
    }
}

// ---------------- stage 4b: 1-warp serial sweep per (image,level) ---------
__global__ __launch_bounds__(32) void k_sweep() {
    int p = blockIdx.x, n = p / NLVL, l = p % NLVL, k = k_of(l), off = l * 1000;
    int lane = threadIdx.x;
    __shared__ unsigned char sv[1000];
    for (int i = lane; i < k; i += 32) sv[i] = g_valid[n][off + i];
    __syncwarp();
    unsigned long long removed = 0;
    unsigned long long buf[8];
#pragma unroll
    for (int q = 0; q < 8; q++)
        buf[q] = (lane < 16) ? g_mask[p][q][lane] : 0ULL;
    for (int ib = 0; ib < k; ib += 8) {
#pragma unroll
        for (int q = 0; q < 8; q++) {
            int i = ib + q;
            unsigned long long row = buf[q];
            unsigned long long wv = __shfl_sync(0xFFFFFFFFu, removed, i >> 6);
            bool keep = sv[i] && !((wv >> (i & 63)) & 1ULL);
            if (keep) removed |= row;
            if (lane == 0) g_kept[n][off + i] = keep ? 1 : 0;
            int ni = ib + 8 + q;
            buf[q] = (lane < 16 && ni < k) ? g_mask[p][ni][lane] : 0ULL;
        }
    }
}

// ---------------- stage 5: stable partition -> first 1000 outputs ---------
__global__ __launch_bounds__(1024) void k_final(float* out) {
    int n = blockIdx.x, t = threadIdx.x;
    __shared__ int wb[33];
    int f[5], mloc[5];
    int ls = 0;
#pragma unroll
    for (int q = 0; q < 5; q++) {
        int r = t * 5 + q;
        if (r < MTOT) {
            int m = g_perm[n][r];
            mloc[q] = m;
            f[q] = g_kept[n][m];
        } else {
            mloc[q] = 0;
            f[q] = 0;
        }
        ls += f[q];
    }
    int lane = t & 31, w = t >> 5;
    int x = ls;
#pragma unroll
    for (int d = 1; d < 32; d <<= 1) {
        int y = __shfl_up_sync(0xFFFFFFFFu, x, d);
        if (lane >= d) x += y;
    }
    if (lane == 31) wb[w] = x;
    __syncthreads();
    if (w == 0) {
        int ws = wb[lane], xx = ws;
#pragma unroll
        for (int d = 1; d < 32; d <<= 1) {
            int y = __shfl_up_sync(0xFFFFFFFFu, xx, d);
            if (lane >= d) xx += y;
        }
        wb[lane] = xx - ws;
        if (lane == 31) wb[32] = xx;
    }
    __syncthreads();
    int KT = wb[32];
    int kr = x - ls + wb[w];
#pragma unroll
    for (int q = 0; q < 5; q++) {
        int r = t * 5 + q;
        if (r < MTOT) {
            int pos = f[q] ? kr : KT + (r - kr);
            if (pos < 1000) {
                int m = mloc[q];
                out[((size_t)n * 1000 + pos) * 4 + 0] = g_boxes[n][m][0];
                out[((size_t)n * 1000 + pos) * 4 + 1] = g_boxes[n][m][1];
                out[((size_t)n * 1000 + pos) * 4 + 2] = g_boxes[n][m][2];
                out[((size_t)n * 1000 + pos) * 4 + 3] = g_boxes[n][m][3];
                out[NIMG * 1000 * 4 + (size_t)n * 1000 + pos] =
                    f[q] ? g_fscore[n][m] : NEGV;
            }
            kr += f[q];
        }
    }
}

// ---------------- host launcher ----------------
extern "C" void kernel_launch(void* const* d_in, const int* in_sizes, int n_in,
                              void* d_out, int out_size) {
    Ptrs P;
    bool interleaved = (n_in >= 2 && in_sizes[1] == 3145728);
    for (int l = 0; l < NLVL; l++) {
        if (interleaved) {
            P.logit[l] = (const float*)d_in[3 * l + 0];
            P.delta[l] = (const float*)d_in[3 * l + 1];
            P.anch[l] = (const float*)d_in[3 * l + 2];
        } else {
            P.logit[l] = (const float*)d_in[l];
            P.delta[l] = (const float*)d_in[5 + l];
            P.anch[l] = (const float*)d_in[10 + l];
        }
    }
    float* out = (float*)d_out;

    cudaFuncSetAttribute(k_select, cudaFuncAttributeMaxDynamicSharedMemorySize, 65536);

    k_zero<<<80, 1024>>>();
    k_hist<<<dim3(24, 20), 256>>>(P);
    k_thresh<<<20, 256>>>();
    k_collect<<<dim3(24, 20), 256>>>(P);
    k_select<<<20, 1024, 65536>>>();
    k_decode<<<(NIMG * MTOT + 255) / 256, 256>>>(P);
    k_merge<<<4, 1024>>>();
    k_iou<<<dim3(16, 20), 256>>>();
    k_sweep<<<20, 32>>>();
    k_final<<<4, 1024>>>(out);
}